// round 9
// baseline (speedup 1.0000x reference)
#include <cuda_runtime.h>
#include <math.h>

#define N_MAX   65536
#define NF      64
#define LORD    5
#define RING    2048
#define BLOCK   256          // 8 warps, 2 samples/thread
#define WCAP    512
#define HALF    256
#define M32N    (N_MAX / 32)
#define ZCLAMP  801          // COEFF_VEC_SIZE(807) - (L_ORDER+1)
#define IB_SAMP 1024         // samples per interp block
#define IB_THR  256

// ---------------- device scratch (no allocations allowed) ----------------
__device__ __align__(16) float4 g_vals4[N_MAX * 2];  // per sample: v0..v5, x, z_bits
__device__ int g_m32[M32N];                          // min clamped z per 32-sample block

__device__ __forceinline__ float tin_f(int i) {
    // fp32 knot position, matching jnp.linspace(0,1,64)[i] to ~1 ulp
    return (float)((double)i / 63.0);
}

// ---------------- kernel 1: fused prep (per-block) + spline eval + taps ----------------
__global__ void __launch_bounds__(IB_THR)
interp_kernel(const float* __restrict__ delay, const float* __restrict__ raw,
              const float* __restrict__ exc, int burst, int n) {
    __shared__ float yf[6][NF];
    __shared__ float w[62];
    __shared__ float dpS[6][62];
    __shared__ float Ms[6][64];
    __shared__ float spy[6][64];
    __shared__ float spb[6][63];
    __shared__ float spc[6][63];
    __shared__ float spd[6][63];
    int tid = threadIdx.x;
    if (burst > n) burst = n;

    // --- phase 1: sigmoid coeffs (threads 0..63) + Thomas w table (one spare thread)
    if (tid < NF) {
        float s[LORD]; float sum = 0.f;
        #pragma unroll
        for (int l = 0; l < LORD; l++) {
            s[l] = 1.0f / (1.0f + expf(-raw[tid * LORD + l]));
            sum += s[l];
        }
        #pragma unroll
        for (int l = 0; l < LORD; l++) yf[1 + l][tid] = s[l] / sum;
        yf[0][tid] = delay[tid];
    }
    if (tid == IB_THR - 1) {
        float wv = 0.25f; w[0] = wv;
        #pragma unroll
        for (int k = 1; k < 62; k++) { wv = 1.0f / (4.0f - wv); w[k] = wv; }
    }
    __syncthreads();

    // --- phase 2: Thomas forward/backward (6 threads, scratch in shared)
    if (tid < 6) {
        const float rs = 6.0f * 63.0f * 63.0f;   // 6/h^2
        float yim1 = yf[tid][0];
        float yi   = yf[tid][1];
        float prev = 0.f;
        #pragma unroll
        for (int k = 0; k < 62; k++) {
            float yip1 = yf[tid][k + 2];
            float r = rs * (yip1 - 2.0f * yi + yim1);
            prev = (k == 0) ? r * w[0] : (r - prev) * w[k];
            dpS[tid][k] = prev;
            yim1 = yi; yi = yip1;
        }
        Ms[tid][63] = 0.0f;
        Ms[tid][0]  = 0.0f;
        float mnext = dpS[tid][61];
        Ms[tid][62] = mnext;
        #pragma unroll
        for (int k = 60; k >= 0; k--) {
            mnext = dpS[tid][k] - w[k] * Ms[tid][k + 2];
            Ms[tid][k + 1] = mnext;
        }
        spy[tid][63] = yf[tid][63];
    }
    __syncthreads();

    // --- phase 3: emit interval coefficients (parallel over 6*63)
    for (int e = tid; e < 6 * 63; e += IB_THR) {
        int ch = e / 63, i = e - ch * 63;
        float y0 = yf[ch][i], y1 = yf[ch][i + 1];
        float M0 = Ms[ch][i], M1 = Ms[ch][i + 1];
        float b = (y1 - y0) * 63.0f - (1.0f / 63.0f) * (2.0f * M0 + M1) * (1.0f / 6.0f);
        spy[ch][i] = y0;
        spb[ch][i] = b;
        spc[ch][i] = M0 * 0.5f;
        spd[ch][i] = (M1 - M0) * (63.0f / 6.0f);
    }
    __syncthreads();

    // --- phase 4: evaluate 4 consecutive samples per thread
    const double inv_nm1 = 1.0 / (double)(n - 1);
    int j0 = blockIdx.x * IB_SAMP + tid * 4;
    int zmin = 0x7fffffff;

    #pragma unroll
    for (int q = 0; q < 4; q++) {
        int j = j0 + q;
        if (j >= n) break;
        double td = (double)j * inv_nm1;
        float tf = (float)td;
        int i0 = (int)(td * 63.0);
        if (i0 > 62) i0 = 62;
        if (i0 < 0)  i0 = 0;
        // replicate searchsorted(t_in, t_out, 'right')-1 in fp32 exactly
        while (i0 < 62 && tin_f(i0 + 1) <= tf) i0++;
        while (i0 > 0 && tin_f(i0) > tf) i0--;
        float dt = tf - tin_f(i0);

        float ch[6];
        #pragma unroll
        for (int cc = 0; cc < 6; cc++) {
            ch[cc] = spy[cc][i0] + spb[cc][i0] * dt
                   + spc[cc][i0] * dt * dt + spd[cc][i0] * dt * dt * dt;
        }

        float dl = ch[0];
        float zf = floorf(dl);
        int   z  = (int)zf;
        float alfa = dl - zf;
        float om = 1.0f - alfa;
        float b0 = ch[1], b1 = ch[2], b2 = ch[3], b3 = ch[4], b4 = ch[5];

        int zc = z; if (zc < 0) zc = 0; if (zc > ZCLAMP) zc = ZCLAMP;
        float x = (j < burst) ? exc[j] : 0.0f;

        float4 vA = make_float4(-om * b0,
                                -(alfa * b0 + om * b1),
                                -(alfa * b1 + om * b2),
                                -(alfa * b2 + om * b3));
        float4 vB = make_float4(-(alfa * b3 + om * b4),
                                -alfa * b4,
                                x,
                                __int_as_float(zc));
        g_vals4[(size_t)j * 2]     = vA;
        g_vals4[(size_t)j * 2 + 1] = vB;
        if (zc < zmin) zmin = zc;
    }

    // min over 8 consecutive lanes = one 32-sample block; no atomics needed
    #pragma unroll
    for (int off = 4; off; off >>= 1) {
        int o = __shfl_xor_sync(0xffffffffu, zmin, off);
        if (o < zmin) zmin = o;
    }
    if ((tid & 7) == 0) {
        int mi = j0 >> 5;
        if (mi < M32N) g_m32[mi] = zmin;
    }
}

// ---------------- kernel 2: 8-warp IIR, 2 samples/thread, ring-dump output ----------------
__global__ void __launch_bounds__(BLOCK, 1)
iir_kernel(float* __restrict__ out, int n) {
    __shared__ float ring[RING];
    __shared__ int   sm32[M32N];
    __shared__ int   swb[M32N];   // chunk width if a chunk starts in this 32-block
    int tid = threadIdx.x;
    const float4* __restrict__ vals = g_vals4;

    for (int i = tid; i < RING; i += BLOCK) ring[i] = 0.0f;
    for (int i = tid; i < M32N; i += BLOCK) sm32[i] = g_m32[i];
    __syncthreads();

    // Wb[i] = min(m32[i .. i+17]) + 1, cap WCAP (512).
    for (int i = tid; i < M32N; i += BLOCK) {
        int v = 0x7fffffff;
        #pragma unroll
        for (int k = 0; k < 18; k++) {
            int idx = i + k;
            if (idx < M32N) { int m = sm32[idx]; if (m < v) v = m; }
        }
        int Wv = v + 1;
        if (Wv > WCAP) Wv = WCAP;
        if (Wv < 1)    Wv = 1;
        swb[i] = Wv;
    }
    __syncthreads();

    // ---- schedule prologue: chunks 0..4, buffers for chunks 0..3 ----
    #define WB_AT(pos) swb[((pos) >> 5) < (M32N - 1) ? ((pos) >> 5) : (M32N - 1)]
    int W0 = WB_AT(0);
    int c1 = W0;       int W1 = WB_AT(c1);
    int c2 = c1 + W1;  int W2 = WB_AT(c2);
    int c3 = c2 + W2;  int W3 = WB_AT(c3);
    int s4 = c3 + W3;  int W4 = WB_AT(s4);

    // per-stage buffers: L=sample c+tid, H=sample c+256+tid
    float4 z4 = make_float4(0,0,0,0);
    float4 L0A=z4,L0B=z4,H0A=z4,H0B=z4;
    float4 L1A=z4,L1B=z4,H1A=z4,H1B=z4;
    float4 L2A=z4,L2B=z4,H2A=z4,H2B=z4;
    float4 L3A=z4,L3B=z4,H3A=z4,H3B=z4;

    #define LOADSTAGE(LA_,LB_,HA_,HB_, cs, Ws)                                  \
    {   int tL = (cs) + tid;                                                    \
        if (tid < (Ws) && tL < n)        { LA_ = vals[(size_t)tL*2]; LB_ = vals[(size_t)tL*2+1]; } \
        int tH = (cs) + HALF + tid;                                             \
        if (HALF + tid < (Ws) && tH < n) { HA_ = vals[(size_t)tH*2]; HB_ = vals[(size_t)tH*2+1]; } }

    LOADSTAGE(L0A,L0B,H0A,H0B, 0,  W0);
    LOADSTAGE(L1A,L1B,H1A,H1B, c1, W1);
    LOADSTAGE(L2A,L2B,H2A,H2B, c2, W2);
    LOADSTAGE(L3A,L3B,H3A,H3B, c3, W3);

    // precompute chunk 0: predicates, LDS addresses, store indices
    int  ntL = tid,         ntH = HALF + tid;
    bool pL  = (tid < W0) && (ntL < n);
    bool pH  = (HALF + tid < W0) && (ntH < n);
    int bL = ntL - 1 - __float_as_int(L0B.w);
    int bH = ntH - 1 - __float_as_int(H0B.w);
    int aL0=(bL)&(RING-1), aL1=(bL-1)&(RING-1), aL2=(bL-2)&(RING-1);
    int aL3=(bL-3)&(RING-1), aL4=(bL-4)&(RING-1), aL5=(bL-5)&(RING-1);
    int aH0=(bH)&(RING-1), aH1=(bH-1)&(RING-1), aH2=(bH-2)&(RING-1);
    int aH3=(bH-3)&(RING-1), aH4=(bH-4)&(RING-1), aH5=(bH-5)&(RING-1);

    int c = 0;
    int next_dump = 1024;

    #define ITER(LA_,LB_,HA_,HB_, LyB_, HyB_)                                   \
    {                                                                           \
        int s5 = s4 + W4;                                                       \
        int W5 = WB_AT(s5);                                                     \
        /* bulk output dump: segment [next_dump-1024, next_dump) is final */    \
        if (c >= next_dump) {                                                   \
            int i4 = (next_dump - 1024) + (tid << 2);                           \
            float4 v = *(const float4*)&ring[i4 & (RING - 1)];                  \
            *(float4*)&out[i4] = v;                                             \
            next_dump += 1024;                                                  \
        }                                                                       \
        /* body: post-barrier chain is LDS -> FFMA -> STS only */               \
        if (pL) {                                                               \
            float r0 = ring[aL0], r1 = ring[aL1], r2 = ring[aL2];               \
            float r3 = ring[aL3], r4 = ring[aL4], r5 = ring[aL5];               \
            float p0 = LA_.x * r0 + LA_.z * r2 + LB_.x * r4;                    \
            float p1 = LA_.y * r1 + LA_.w * r3 + LB_.y * r5;                    \
            ring[ntL & (RING - 1)] = LB_.z - p0 - p1;                           \
        }                                                                       \
        if (pH) {                                                               \
            float r0 = ring[aH0], r1 = ring[aH1], r2 = ring[aH2];               \
            float r3 = ring[aH3], r4 = ring[aH4], r5 = ring[aH5];               \
            float p0 = HA_.x * r0 + HA_.z * r2 + HB_.x * r4;                    \
            float p1 = HA_.y * r1 + HA_.w * r3 + HB_.y * r5;                    \
            ring[ntH & (RING - 1)] = HB_.z - p0 - p1;                           \
        }                                                                       \
        /* refill this stage for chunk k+4 (in place, zero moves) */            \
        LOADSTAGE(LA_,LB_,HA_,HB_, s4, W4);                                     \
        /* precompute chunk k+1 (its buffers resident for 3 chunks) */          \
        {   int cn = c + W0;                                                    \
            ntL = cn + tid;  ntH = cn + HALF + tid;                             \
            pL = (tid < W1) && (ntL < n);                                       \
            pH = (HALF + tid < W1) && (ntH < n);                                \
            bL = ntL - 1 - __float_as_int(LyB_.w);                              \
            bH = ntH - 1 - __float_as_int(HyB_.w);                              \
            aL0=(bL)&(RING-1); aL1=(bL-1)&(RING-1); aL2=(bL-2)&(RING-1);        \
            aL3=(bL-3)&(RING-1); aL4=(bL-4)&(RING-1); aL5=(bL-5)&(RING-1);      \
            aH0=(bH)&(RING-1); aH1=(bH-1)&(RING-1); aH2=(bH-2)&(RING-1);        \
            aH3=(bH-3)&(RING-1); aH4=(bH-4)&(RING-1); aH5=(bH-5)&(RING-1);      \
            c = cn; }                                                           \
        __syncthreads();   /* single barrier per chunk */                       \
        W0 = W1; W1 = W2; W2 = W3; W3 = W4; W4 = W5; s4 = s5;                   \
    }

    while (c < n) {
        ITER(L0A,L0B,H0A,H0B, L1B,H1B);
        if (c >= n) break;
        ITER(L1A,L1B,H1A,H1B, L2B,H2B);
        if (c >= n) break;
        ITER(L2A,L2B,H2A,H2B, L3B,H3B);
        if (c >= n) break;
        ITER(L3A,L3B,H3A,H3B, L0B,H0B);
    }
    #undef ITER
    #undef LOADSTAGE
    #undef WB_AT

    // flush remaining (< 2048) samples
    __syncthreads();
    for (int i = (next_dump - 1024) + tid; i < n; i += BLOCK)
        out[i] = ring[i & (RING - 1)];
}

// ---------------- launch ----------------
extern "C" void kernel_launch(void* const* d_in, const int* in_sizes, int n_in,
                              void* d_out, int out_size) {
    const float* delay = (const float*)d_in[0];
    const float* raw   = (const float*)d_in[1];
    const float* exc   = (const float*)d_in[2];
    int burst = in_sizes[2];
    int n = out_size;
    if (n > N_MAX) n = N_MAX;

    int iblocks = (n + IB_SAMP - 1) / IB_SAMP;
    interp_kernel<<<iblocks, IB_THR>>>(delay, raw, exc, burst, n);
    iir_kernel<<<1, BLOCK>>>((float*)d_out, n);
}

// round 10
// speedup vs baseline: 1.0907x; 1.0907x over previous
#include <cuda_runtime.h>
#include <math.h>

#define N_MAX   65536
#define NF      64
#define LORD    5
#define RING    2048
#define BLOCK   448          // 14 warps, 1 sample/thread
#define WCAP    448
#define M32N    (N_MAX / 32)
#define ZCLAMP  801          // COEFF_VEC_SIZE(807) - (L_ORDER+1)
#define IB_SAMP 1024         // samples per interp block
#define IB_THR  256

// ---------------- device scratch (no allocations allowed) ----------------
__device__ __align__(16) float4 g_vals4[N_MAX * 2];  // per sample: v0..v5, x, z_bits
__device__ int g_m32[M32N];                          // min clamped z per 32-sample block

__device__ __forceinline__ float tin_f(int i) {
    // fp32 knot position, matching jnp.linspace(0,1,64)[i] to ~1 ulp
    return (float)((double)i / 63.0);
}

// ---------------- kernel 1: fused prep (per-block) + spline eval + taps ----------------
__global__ void __launch_bounds__(IB_THR)
interp_kernel(const float* __restrict__ delay, const float* __restrict__ raw,
              const float* __restrict__ exc, int burst, int n) {
    __shared__ float yf[6][NF];
    __shared__ float w[62];
    __shared__ float dpS[6][62];
    __shared__ float Ms[6][64];
    __shared__ float spy[6][64];
    __shared__ float spb[6][63];
    __shared__ float spc[6][63];
    __shared__ float spd[6][63];
    int tid = threadIdx.x;
    if (burst > n) burst = n;

    // --- phase 1: sigmoid coeffs (threads 0..63) + Thomas w table (one spare thread)
    if (tid < NF) {
        float s[LORD]; float sum = 0.f;
        #pragma unroll
        for (int l = 0; l < LORD; l++) {
            s[l] = 1.0f / (1.0f + expf(-raw[tid * LORD + l]));
            sum += s[l];
        }
        #pragma unroll
        for (int l = 0; l < LORD; l++) yf[1 + l][tid] = s[l] / sum;
        yf[0][tid] = delay[tid];
    }
    if (tid == IB_THR - 1) {
        float wv = 0.25f; w[0] = wv;
        #pragma unroll
        for (int k = 1; k < 62; k++) { wv = 1.0f / (4.0f - wv); w[k] = wv; }
    }
    __syncthreads();

    // --- phase 2: Thomas forward/backward (6 threads, scratch in shared)
    if (tid < 6) {
        const float rs = 6.0f * 63.0f * 63.0f;   // 6/h^2
        float yim1 = yf[tid][0];
        float yi   = yf[tid][1];
        float prev = 0.f;
        #pragma unroll
        for (int k = 0; k < 62; k++) {
            float yip1 = yf[tid][k + 2];
            float r = rs * (yip1 - 2.0f * yi + yim1);
            prev = (k == 0) ? r * w[0] : (r - prev) * w[k];
            dpS[tid][k] = prev;
            yim1 = yi; yi = yip1;
        }
        Ms[tid][63] = 0.0f;
        Ms[tid][0]  = 0.0f;
        float mnext = dpS[tid][61];
        Ms[tid][62] = mnext;
        #pragma unroll
        for (int k = 60; k >= 0; k--) {
            mnext = dpS[tid][k] - w[k] * Ms[tid][k + 2];
            Ms[tid][k + 1] = mnext;
        }
        spy[tid][63] = yf[tid][63];
    }
    __syncthreads();

    // --- phase 3: emit interval coefficients (parallel over 6*63)
    for (int e = tid; e < 6 * 63; e += IB_THR) {
        int ch = e / 63, i = e - ch * 63;
        float y0 = yf[ch][i], y1 = yf[ch][i + 1];
        float M0 = Ms[ch][i], M1 = Ms[ch][i + 1];
        float b = (y1 - y0) * 63.0f - (1.0f / 63.0f) * (2.0f * M0 + M1) * (1.0f / 6.0f);
        spy[ch][i] = y0;
        spb[ch][i] = b;
        spc[ch][i] = M0 * 0.5f;
        spd[ch][i] = (M1 - M0) * (63.0f / 6.0f);
    }
    __syncthreads();

    // --- phase 4: evaluate 4 consecutive samples per thread
    const double inv_nm1 = 1.0 / (double)(n - 1);
    int j0 = blockIdx.x * IB_SAMP + tid * 4;
    int zmin = 0x7fffffff;

    #pragma unroll
    for (int q = 0; q < 4; q++) {
        int j = j0 + q;
        if (j >= n) break;
        double td = (double)j * inv_nm1;
        float tf = (float)td;
        int i0 = (int)(td * 63.0);
        if (i0 > 62) i0 = 62;
        if (i0 < 0)  i0 = 0;
        // replicate searchsorted(t_in, t_out, 'right')-1 in fp32 exactly
        while (i0 < 62 && tin_f(i0 + 1) <= tf) i0++;
        while (i0 > 0 && tin_f(i0) > tf) i0--;
        float dt = tf - tin_f(i0);

        float ch[6];
        #pragma unroll
        for (int cc = 0; cc < 6; cc++) {
            ch[cc] = spy[cc][i0] + spb[cc][i0] * dt
                   + spc[cc][i0] * dt * dt + spd[cc][i0] * dt * dt * dt;
        }

        float dl = ch[0];
        float zf = floorf(dl);
        int   z  = (int)zf;
        float alfa = dl - zf;
        float om = 1.0f - alfa;
        float b0 = ch[1], b1 = ch[2], b2 = ch[3], b3 = ch[4], b4 = ch[5];

        int zc = z; if (zc < 0) zc = 0; if (zc > ZCLAMP) zc = ZCLAMP;
        float x = (j < burst) ? exc[j] : 0.0f;

        float4 vA = make_float4(-om * b0,
                                -(alfa * b0 + om * b1),
                                -(alfa * b1 + om * b2),
                                -(alfa * b2 + om * b3));
        float4 vB = make_float4(-(alfa * b3 + om * b4),
                                -alfa * b4,
                                x,
                                __int_as_float(zc));
        g_vals4[(size_t)j * 2]     = vA;
        g_vals4[(size_t)j * 2 + 1] = vB;
        if (zc < zmin) zmin = zc;
    }

    // min over 8 consecutive lanes = one 32-sample block; no atomics needed
    #pragma unroll
    for (int off = 4; off; off >>= 1) {
        int o = __shfl_xor_sync(0xffffffffu, zmin, off);
        if (o < zmin) zmin = o;
    }
    if ((tid & 7) == 0) {
        int mi = j0 >> 5;
        if (mi < M32N) g_m32[mi] = zmin;
    }
}

// ---------------- kernel 2: 14-warp IIR, mirrored ring, ring-dump output ----------------
__global__ void __launch_bounds__(BLOCK, 1)
iir_kernel(float* __restrict__ out, int n) {
    __shared__ __align__(16) float ringraw[RING + 8];  // [0..7] mirror of logical 2040..2047
    __shared__ int sm32[M32N];
    __shared__ int swb[M32N];     // chunk width if a chunk starts in this 32-block
    int tid = threadIdx.x;
    const float4* __restrict__ vals = g_vals4;
    float* ringp = ringraw + 8;   // logical slot s at ringp[s]; ringp[-k] = logical RING-k

    for (int i = tid; i < RING + 8; i += BLOCK) ringraw[i] = 0.0f;
    for (int i = tid; i < M32N; i += BLOCK) sm32[i] = g_m32[i];
    __syncthreads();

    // Wb[i] = min(m32[i .. i+14]) + 1, cap WCAP (448).
    // start max in block i = 32i+31; last sample = start+W-1 <= 32i+478 < 32(i+15)
    for (int i = tid; i < M32N; i += BLOCK) {
        int v = 0x7fffffff;
        #pragma unroll
        for (int k = 0; k < 15; k++) {
            int idx = i + k;
            if (idx < M32N) { int m = sm32[idx]; if (m < v) v = m; }
        }
        int Wv = v + 1;
        if (Wv > WCAP) Wv = WCAP;
        if (Wv < 1)    Wv = 1;
        swb[i] = Wv;
    }
    __syncthreads();

    // ---- schedule prologue: chunks 0..4, buffers for chunks 0..3 ----
    #define WB_AT(pos) swb[((pos) >> 5) < (M32N - 1) ? ((pos) >> 5) : (M32N - 1)]
    int W0 = WB_AT(0);
    int c1 = W0;       int W1 = WB_AT(c1);
    int c2 = c1 + W1;  int W2 = WB_AT(c2);
    int c3 = c2 + W2;  int W3 = WB_AT(c3);
    int s4 = c3 + W3;  int W4 = WB_AT(s4);

    float4 z4 = make_float4(0,0,0,0);
    float4 A0=z4,B0=z4, A1=z4,B1=z4, A2=z4,B2=z4, A3=z4,B3=z4;
    if (tid < W0 && tid < n) { A0 = vals[(size_t)tid*2]; B0 = vals[(size_t)tid*2+1]; }
    { int t = c1 + tid; if (tid < W1 && t < n) { A1 = vals[(size_t)t*2]; B1 = vals[(size_t)t*2+1]; } }
    { int t = c2 + tid; if (tid < W2 && t < n) { A2 = vals[(size_t)t*2]; B2 = vals[(size_t)t*2+1]; } }
    { int t = c3 + tid; if (tid < W3 && t < n) { A3 = vals[(size_t)t*2]; B3 = vals[(size_t)t*2+1]; } }

    // precompute chunk 0: predicate, tap base index, store slot
    bool p  = (tid < W0) && (tid < n);
    int  ai = (tid - 1 - __float_as_int(B0.w)) & (RING - 1);
    int  ns = tid & (RING - 1);

    int c = 0;
    int next_dump = 1024;

    #define ITER(Ax, Bx, ByN)                                                   \
    {                                                                           \
        int s5 = s4 + W4;                                                       \
        int W5 = WB_AT(s5);                                                     \
        /* bulk output dump: segment [next_dump-1024, next_dump) is final */    \
        if (c >= next_dump) {                                                   \
            if (tid < 256) {                                                    \
                int i4 = (next_dump - 1024) + (tid << 2);                       \
                float4 v = *(const float4*)&ringp[i4 & (RING - 1)];             \
                *(float4*)&out[i4] = v;                                         \
            }                                                                   \
            next_dump += 1024;                                                  \
        }                                                                       \
        /* body: post-barrier chain is LDS(+imm) -> FFMA -> STS only */         \
        if (p) {                                                                \
            float r0 = ringp[ai];                                               \
            float r1 = ringp[ai - 1];                                           \
            float r2 = ringp[ai - 2];                                           \
            float r3 = ringp[ai - 3];                                           \
            float r4 = ringp[ai - 4];                                           \
            float r5 = ringp[ai - 5];                                           \
            float p0 = Ax.x * r0 + Ax.z * r2 + Bx.x * r4;                       \
            float p1 = Ax.y * r1 + Ax.w * r3 + Bx.y * r5;                       \
            float acc = Bx.z - p0 - p1;                                         \
            ringp[ns] = acc;                                                    \
            if (ns >= RING - 5) ringp[ns - RING] = acc;  /* maintain mirror */  \
        }                                                                       \
        /* refill this stage for chunk k+4 (in place, zero moves) */            \
        { int tp = s4 + tid;                                                    \
          if (tid < W4 && tp < n) {                                             \
              Ax = vals[(size_t)tp * 2];                                        \
              Bx = vals[(size_t)tp * 2 + 1];                                    \
          } }                                                                   \
        /* precompute chunk k+1 (its buffer resident for 3 chunks) */           \
        { int cn = c + W0;                                                      \
          int t1 = cn + tid;                                                    \
          p  = (tid < W1) && (t1 < n);                                          \
          ai = (t1 - 1 - __float_as_int(ByN.w)) & (RING - 1);                   \
          ns = t1 & (RING - 1);                                                 \
          c  = cn; }                                                            \
        __syncthreads();   /* single barrier per chunk */                       \
        W0 = W1; W1 = W2; W2 = W3; W3 = W4; W4 = W5; s4 = s5;                   \
    }

    while (c < n) {
        ITER(A0, B0, B1);
        if (c >= n) break;
        ITER(A1, B1, B2);
        if (c >= n) break;
        ITER(A2, B2, B3);
        if (c >= n) break;
        ITER(A3, B3, B0);
    }
    #undef ITER
    #undef WB_AT

    // flush remaining (< 2048) samples
    __syncthreads();
    for (int i = (next_dump - 1024) + tid; i < n; i += BLOCK)
        out[i] = ringp[i & (RING - 1)];
}

// ---------------- launch ----------------
extern "C" void kernel_launch(void* const* d_in, const int* in_sizes, int n_in,
                              void* d_out, int out_size) {
    const float* delay = (const float*)d_in[0];
    const float* raw   = (const float*)d_in[1];
    const float* exc   = (const float*)d_in[2];
    int burst = in_sizes[2];
    int n = out_size;
    if (n > N_MAX) n = N_MAX;

    int iblocks = (n + IB_SAMP - 1) / IB_SAMP;
    interp_kernel<<<iblocks, IB_THR>>>(delay, raw, exc, burst, n);
    iir_kernel<<<1, BLOCK>>>((float*)d_out, n);
}